// round 5
// baseline (speedup 1.0000x reference)
#include <cuda_runtime.h>
#include <math.h>

#define BATCH   4
#define S_LEN   2048
#define DMODEL  1024
#define DKDIM   128

// ---------------- scratch (device globals; no runtime allocation) ----------
__device__ float g_Q[BATCH * S_LEN * DKDIM];       // 4 MB
__device__ float g_K[BATCH * S_LEN * DKDIM];       // 4 MB
__device__ float g_V[BATCH * S_LEN * DMODEL];      // 32 MB
__device__ float g_P[(size_t)BATCH * S_LEN * S_LEN]; // 64 MB
__device__ float g_vmean[BATCH * DMODEL];
__device__ int   g_len[BATCH];

// ---------------- mask prep: detect dtype + compute per-batch lengths ------
// padding_mask[b,s] = (s >= len[b]), len[b] in [1024, 2047].
// Byte 2047 of the buffer: ==1 iff 1-byte layout (mask[0,2047] is always true);
// ==0 for any 4-byte layout (high byte of element 511, which is always 0).
__global__ void prep_len_kernel(const unsigned char* __restrict__ mask) {
    __shared__ int sred[256];
    int b = blockIdx.x;
    int tid = threadIdx.x;
    bool byte_layout = (mask[2047] != 0);
    int cnt = 0;
    if (byte_layout) {
        const unsigned char* m = mask + b * S_LEN;
        for (int s = tid; s < S_LEN; s += 256) cnt += (m[s] == 0);
    } else {
        const unsigned int* m = (const unsigned int*)mask + b * S_LEN;
        for (int s = tid; s < S_LEN; s += 256) cnt += (m[s] == 0u);
    }
    sred[tid] = cnt;
    __syncthreads();
    for (int off = 128; off > 0; off >>= 1) {
        if (tid < off) sred[tid] += sred[tid + off];
        __syncthreads();
    }
    if (tid == 0) g_len[b] = sred[0];
}

// ---------------- shared SGEMM tile body ------------------------------------
// C[bm:bm+128, bn:bn+128] = A[bm:, kBegin:kEnd] * B[kBegin:kEnd, bn:] (+bias)
// A row-major with leading dim ldA, B row-major with leading dim N (= ldC).
// 256 threads, 8x8 microtile per thread, BK = 8.
__device__ __forceinline__ void sgemm_block(
    const float* __restrict__ A, const float* __restrict__ B,
    const float* __restrict__ bias, float* __restrict__ C,
    int N, int ldA, int bm, int bn, int kBegin, int kEnd)
{
    __shared__ float As[8][128];
    __shared__ float Bs[8][128];

    const int tid  = threadIdx.x;
    const int arow = tid >> 1;           // 0..127
    const int acol = (tid & 1) << 2;     // 0 or 4
    const int brow = tid >> 5;           // 0..7
    const int bcol = (tid & 31) << 2;    // 0..124
    const int tm   = (tid >> 4) << 3;    // 0..120
    const int tn   = (tid & 15) << 3;    // 0..120

    float acc[8][8];
    #pragma unroll
    for (int i = 0; i < 8; i++)
        #pragma unroll
        for (int j = 0; j < 8; j++) acc[i][j] = 0.0f;

    const float* Ap = A + (size_t)(bm + arow) * ldA + acol;
    const float* Bp = B + bn + bcol;

    for (int k0 = kBegin; k0 < kEnd; k0 += 8) {
        float4 a4 = *(const float4*)(Ap + k0);
        float4 b4 = *(const float4*)(Bp + (size_t)(k0 + brow) * N);
        As[acol + 0][arow] = a4.x;
        As[acol + 1][arow] = a4.y;
        As[acol + 2][arow] = a4.z;
        As[acol + 3][arow] = a4.w;
        *(float4*)&Bs[brow][bcol] = b4;
        __syncthreads();

        #pragma unroll
        for (int kk = 0; kk < 8; kk++) {
            float ra[8], rb[8];
            *(float4*)&ra[0] = *(const float4*)&As[kk][tm];
            *(float4*)&ra[4] = *(const float4*)&As[kk][tm + 4];
            *(float4*)&rb[0] = *(const float4*)&Bs[kk][tn];
            *(float4*)&rb[4] = *(const float4*)&Bs[kk][tn + 4];
            #pragma unroll
            for (int i = 0; i < 8; i++)
                #pragma unroll
                for (int j = 0; j < 8; j++)
                    acc[i][j] = fmaf(ra[i], rb[j], acc[i][j]);
        }
        __syncthreads();
    }

    #pragma unroll
    for (int i = 0; i < 8; i++) {
        float* Crow = C + (size_t)(bm + tm + i) * N + bn + tn;
        #pragma unroll
        for (int j = 0; j < 8; j += 4) {
            float4 o;
            o.x = acc[i][j + 0];
            o.y = acc[i][j + 1];
            o.z = acc[i][j + 2];
            o.w = acc[i][j + 3];
            if (bias) {
                o.x += bias[bn + tn + j + 0];
                o.y += bias[bn + tn + j + 1];
                o.z += bias[bn + tn + j + 2];
                o.w += bias[bn + tn + j + 3];
            }
            *(float4*)(Crow + j) = o;
        }
    }
}

// ---------------- projections -----------------------------------------------
// Q = x @ Wq + bq, K = x @ Wk + bk  (grid.z selects Q vs K)
__global__ void __launch_bounds__(256) proj_qk_kernel(
    const float* __restrict__ x,
    const float* __restrict__ Wq, const float* __restrict__ bq,
    const float* __restrict__ Wk, const float* __restrict__ bk)
{
    const float* W    = blockIdx.z ? Wk  : Wq;
    const float* bias = blockIdx.z ? bk  : bq;
    float*       Cout = blockIdx.z ? g_K : g_Q;
    sgemm_block(x, W, bias, Cout, DKDIM, DMODEL, blockIdx.y * 128, 0, 0, DMODEL);
}

// V = x @ Wv + bv
__global__ void __launch_bounds__(256) proj_v_kernel(
    const float* __restrict__ x,
    const float* __restrict__ Wv, const float* __restrict__ bv)
{
    sgemm_block(x, Wv, bv, g_V, DMODEL, DMODEL,
                blockIdx.y * 128, blockIdx.x * 128, 0, DMODEL);
}

// ---------------- vmean: per-batch mean of V rows (for padded queries) ------
__global__ void vmean_kernel() {
    int b   = blockIdx.y;
    int col = blockIdx.x * 256 + threadIdx.x;   // grid.x = 4 -> 1024 cols
    const float* V = g_V + (size_t)b * S_LEN * DMODEL + col;
    float s = 0.0f;
    #pragma unroll 4
    for (int k = 0; k < S_LEN; k++) s += V[(size_t)k * DMODEL];
    g_vmean[b * DMODEL + col] = s * (1.0f / S_LEN);
}

// ---------------- scores: P = Q K^T / sqrt(DK), lower-triangle tiles only ---
__global__ void __launch_bounds__(256) scores_kernel() {
    int b   = blockIdx.y;
    int idx = blockIdx.x;                 // 0..135 lower-triangle tile pairs
    int qt  = (int)((sqrtf(8.0f * idx + 1.0f) - 1.0f) * 0.5f);
    while ((qt + 1) * (qt + 2) / 2 <= idx) qt++;
    while (qt * (qt + 1) / 2 > idx) qt--;
    int kt = idx - qt * (qt + 1) / 2;

    __shared__ float As[8][128];
    __shared__ float Bs[8][128];

    const int tid  = threadIdx.x;
    const int row  = tid >> 1;
    const int col4 = (tid & 1) << 2;
    const int tm   = (tid >> 4) << 3;
    const int tn   = (tid & 15) << 3;

    const float* Qp = g_Q + ((size_t)b * S_LEN + (size_t)qt * 128 + row) * DKDIM + col4;
    const float* Kp = g_K + ((size_t)b * S_LEN + (size_t)kt * 128 + row) * DKDIM + col4;

    float acc[8][8];
    #pragma unroll
    for (int i = 0; i < 8; i++)
        #pragma unroll
        for (int j = 0; j < 8; j++) acc[i][j] = 0.0f;

    for (int d0 = 0; d0 < DKDIM; d0 += 8) {
        float4 a4 = *(const float4*)(Qp + d0);
        float4 b4 = *(const float4*)(Kp + d0);
        As[col4 + 0][row] = a4.x; As[col4 + 1][row] = a4.y;
        As[col4 + 2][row] = a4.z; As[col4 + 3][row] = a4.w;
        Bs[col4 + 0][row] = b4.x; Bs[col4 + 1][row] = b4.y;
        Bs[col4 + 2][row] = b4.z; Bs[col4 + 3][row] = b4.w;
        __syncthreads();

        #pragma unroll
        for (int kk = 0; kk < 8; kk++) {
            float ra[8], rb[8];
            *(float4*)&ra[0] = *(const float4*)&As[kk][tm];
            *(float4*)&ra[4] = *(const float4*)&As[kk][tm + 4];
            *(float4*)&rb[0] = *(const float4*)&Bs[kk][tn];
            *(float4*)&rb[4] = *(const float4*)&Bs[kk][tn + 4];
            #pragma unroll
            for (int i = 0; i < 8; i++)
                #pragma unroll
                for (int j = 0; j < 8; j++)
                    acc[i][j] = fmaf(ra[i], rb[j], acc[i][j]);
        }
        __syncthreads();
    }

    const float scale = 0.0883883476483184f;  // 1/sqrt(128)
    #pragma unroll
    for (int i = 0; i < 8; i++) {
        int q = qt * 128 + tm + i;
        float* Prow = g_P + ((size_t)b * S_LEN + q) * S_LEN + kt * 128 + tn;
        #pragma unroll
        for (int j = 0; j < 8; j += 4) {
            float4 o;
            int kbase = kt * 128 + tn + j;
            o.x = (kbase + 0 > q) ? -1e30f : acc[i][j + 0] * scale;
            o.y = (kbase + 1 > q) ? -1e30f : acc[i][j + 1] * scale;
            o.z = (kbase + 2 > q) ? -1e30f : acc[i][j + 2] * scale;
            o.w = (kbase + 3 > q) ? -1e30f : acc[i][j + 3] * scale;
            *(float4*)(Prow + j) = o;
        }
    }
}

// ---------------- row softmax over tile-aligned prefix ----------------------
__global__ void __launch_bounds__(256) softmax_kernel() {
    __shared__ float buf[S_LEN];
    __shared__ float red[8];
    __shared__ float bcast;

    int b = blockIdx.y, q = blockIdx.x;
    int tid = threadIdx.x;
    int len = g_len[b];
    int Kend = ((q >> 7) + 1) << 7;        // tile-aligned, <= 2048
    float* row = g_P + ((size_t)b * S_LEN + q) * S_LEN;

    if (q >= len) {                        // padded query: zero the prefix
        for (int k = tid; k < Kend; k += 256) row[k] = 0.0f;
        return;
    }

    // pass 1: max (diagonal entry guarantees max > -1e30)
    float m = -3.4e38f;
    for (int k = tid; k < Kend; k += 256) {
        float v = row[k];
        buf[k] = v;
        m = fmaxf(m, v);
    }
    #pragma unroll
    for (int off = 16; off; off >>= 1) m = fmaxf(m, __shfl_xor_sync(0xffffffffu, m, off));
    if ((tid & 31) == 0) red[tid >> 5] = m;
    __syncthreads();
    if (tid == 0) {
        float mm = red[0];
        #pragma unroll
        for (int i = 1; i < 8; i++) mm = fmaxf(mm, red[i]);
        bcast = mm;
    }
    __syncthreads();
    m = bcast;
    __syncthreads();

    // pass 2: exp + sum (entries k>q are -1e30 -> exp underflows to 0; zero them anyway)
    float s = 0.0f;
    for (int k = tid; k < Kend; k += 256) {
        float v = (k <= q) ? __expf(buf[k] - m) : 0.0f;
        buf[k] = v;
        s += v;
    }
    #pragma unroll
    for (int off = 16; off; off >>= 1) s += __shfl_xor_sync(0xffffffffu, s, off);
    if ((tid & 31) == 0) red[tid >> 5] = s;
    __syncthreads();
    if (tid == 0) {
        float ss = red[0];
        #pragma unroll
        for (int i = 1; i < 8; i++) ss += red[i];
        bcast = 1.0f / ss;
    }
    __syncthreads();
    float inv = bcast;

    for (int k = tid; k < Kend; k += 256) row[k] = buf[k] * inv;
}

// ---------------- out = P @ V, causal-blocked --------------------------------
__global__ void __launch_bounds__(256) pv_kernel(float* __restrict__ out) {
    int b  = blockIdx.z;
    int qt = blockIdx.y;
    const float* A = g_P + (size_t)b * S_LEN * S_LEN;
    const float* V = g_V + (size_t)b * S_LEN * DMODEL;
    float*       C = out + (size_t)b * S_LEN * DMODEL;
    sgemm_block(A, V, nullptr, C, DMODEL, S_LEN,
                qt * 128, blockIdx.x * 128, 0, (qt + 1) * 128);
}

// ---------------- overwrite padded-query rows with vmean ---------------------
__global__ void fill_padded_kernel(float* __restrict__ out) {
    int b = blockIdx.y, q = blockIdx.x;
    if (q < g_len[b]) return;
    const float* vm = g_vmean + b * DMODEL;
    float* o = out + ((size_t)b * S_LEN + q) * DMODEL;
    for (int i = threadIdx.x; i < DMODEL; i += 256) o[i] = vm[i];
}

// ---------------- launch ------------------------------------------------------
extern "C" void kernel_launch(void* const* d_in, const int* in_sizes, int n_in,
                              void* d_out, int out_size) {
    const float*         x    = (const float*)d_in[0];
    const unsigned char* mask = (const unsigned char*)d_in[1];
    const float* Wq = (const float*)d_in[2];
    const float* bq = (const float*)d_in[3];
    const float* Wk = (const float*)d_in[4];
    const float* bk = (const float*)d_in[5];
    const float* Wv = (const float*)d_in[6];
    const float* bv = (const float*)d_in[7];
    float* out = (float*)d_out;

    prep_len_kernel<<<BATCH, 256>>>(mask);
    proj_qk_kernel<<<dim3(1, 64, 2), 256>>>(x, Wq, bq, Wk, bk);
    proj_v_kernel<<<dim3(8, 64), 256>>>(x, Wv, bv);
    vmean_kernel<<<dim3(4, BATCH), 256>>>();
    scores_kernel<<<dim3(136, BATCH), 256>>>();
    softmax_kernel<<<dim3(S_LEN, BATCH), 256>>>();
    pv_kernel<<<dim3(8, 16, BATCH), 256>>>(out);
    fill_padded_kernel<<<dim3(S_LEN, BATCH), 256>>>(out);
}

// round 6
// speedup vs baseline: 1.2268x; 1.2268x over previous
#include <cuda_runtime.h>
#include <math.h>

#define BATCH   4
#define S_LEN   2048
#define DMODEL  1024
#define DKDIM   128

// ---------------- scratch (device globals; no runtime allocation) ----------
__device__ float g_Q[BATCH * S_LEN * DKDIM];         // 4 MB
__device__ float g_K[BATCH * S_LEN * DKDIM];         // 4 MB
__device__ float g_V[BATCH * S_LEN * DMODEL];        // 32 MB
__device__ float g_P[(size_t)BATCH * S_LEN * S_LEN]; // 64 MB
__device__ float g_vmean[BATCH * DMODEL];
__device__ int   g_len[BATCH];

// ---------------- packed f32x2 helpers (sm_103a) -----------------------------
__device__ __forceinline__ unsigned long long pack2(float lo, float hi) {
    unsigned long long r;
    asm("mov.b64 %0, {%1, %2};" : "=l"(r) : "f"(lo), "f"(hi));
    return r;
}
__device__ __forceinline__ void fma2(unsigned long long& d,
                                     unsigned long long a, unsigned long long b) {
    asm("fma.rn.f32x2 %0, %1, %2, %0;" : "+l"(d) : "l"(a), "l"(b));
}
__device__ __forceinline__ void unpack2(unsigned long long v, float& lo, float& hi) {
    asm("mov.b64 {%0, %1}, %2;" : "=f"(lo), "=f"(hi) : "l"(v));
}

// ---------------- mask prep: detect dtype + compute per-batch lengths ------
// padding_mask[b,s] = (s >= len[b]), len[b] in [1024, 2047].
// Byte 2047: ==1 iff 1-byte layout (mask[0,2047] always true); ==0 for 4-byte
// layout (high byte of element 511, never padded).
__global__ void prep_len_kernel(const unsigned char* __restrict__ mask) {
    __shared__ int sred[256];
    int b = blockIdx.x;
    int tid = threadIdx.x;
    // zero vmean accumulators (4 floats per thread per block)
    #pragma unroll
    for (int i = 0; i < 4; i++)
        g_vmean[b * DMODEL + tid + i * 256] = 0.0f;

    bool byte_layout = (mask[2047] != 0);
    int cnt = 0;
    if (byte_layout) {
        const unsigned char* m = mask + b * S_LEN;
        for (int s = tid; s < S_LEN; s += 256) cnt += (m[s] == 0);
    } else {
        const unsigned int* m = (const unsigned int*)mask + b * S_LEN;
        for (int s = tid; s < S_LEN; s += 256) cnt += (m[s] == 0u);
    }
    sred[tid] = cnt;
    __syncthreads();
    for (int off = 128; off > 0; off >>= 1) {
        if (tid < off) sred[tid] += sred[tid + off];
        __syncthreads();
    }
    if (tid == 0) g_len[b] = sred[0];
}

// ---------------- f32x2 microtile: 8x8 per thread, 8 k-steps ----------------
// acc2[i][j] holds (acc[2i][j], acc[2i+1][j]) packed along M.
__device__ __forceinline__ void microtile8_f32x2(
    const float (*As)[128], const float (*Bs)[128],
    int tm, int tn, unsigned long long acc2[4][8])
{
    #pragma unroll
    for (int kk = 0; kk < 8; kk++) {
        const ulonglong2* ap = (const ulonglong2*)&As[kk][tm];
        ulonglong2 a01 = ap[0];
        ulonglong2 a23 = ap[1];
        unsigned long long ra2[4] = { a01.x, a01.y, a23.x, a23.y };
        float rb[8];
        *(float4*)&rb[0] = *(const float4*)&Bs[kk][tn];
        *(float4*)&rb[4] = *(const float4*)&Bs[kk][tn + 4];
        #pragma unroll
        for (int j = 0; j < 8; j++) {
            unsigned long long bb = pack2(rb[j], rb[j]);
            #pragma unroll
            for (int i = 0; i < 4; i++)
                fma2(acc2[i][j], ra2[i], bb);
        }
    }
}

// ---------------- shared SGEMM tile body (f32x2) -----------------------------
// C[bm:bm+128, bn:bn+128] = A[bm:, kBegin:kEnd] * B[kBegin:kEnd, bn:] (+bias)
__device__ __forceinline__ void sgemm_block(
    const float* __restrict__ A, const float* __restrict__ B,
    const float* __restrict__ bias, float* __restrict__ C,
    int N, int ldA, int bm, int bn, int kBegin, int kEnd)
{
    __shared__ float As[8][128];
    __shared__ float Bs[8][128];

    const int tid  = threadIdx.x;
    const int arow = tid >> 1;           // 0..127
    const int acol = (tid & 1) << 2;     // 0 or 4
    const int brow = tid >> 5;           // 0..7
    const int bcol = (tid & 31) << 2;    // 0..124
    const int tm   = (tid >> 4) << 3;    // 0..120
    const int tn   = (tid & 15) << 3;    // 0..120

    unsigned long long acc2[4][8];
    #pragma unroll
    for (int i = 0; i < 4; i++)
        #pragma unroll
        for (int j = 0; j < 8; j++) acc2[i][j] = 0ULL;

    const float* Ap = A + (size_t)(bm + arow) * ldA + acol;
    const float* Bp = B + bn + bcol;

    for (int k0 = kBegin; k0 < kEnd; k0 += 8) {
        float4 a4 = *(const float4*)(Ap + k0);
        float4 b4 = *(const float4*)(Bp + (size_t)(k0 + brow) * N);
        As[acol + 0][arow] = a4.x;
        As[acol + 1][arow] = a4.y;
        As[acol + 2][arow] = a4.z;
        As[acol + 3][arow] = a4.w;
        *(float4*)&Bs[brow][bcol] = b4;
        __syncthreads();

        microtile8_f32x2(As, Bs, tm, tn, acc2);
        __syncthreads();
    }

    // epilogue: unpack + optional bias + store
    float bsv[8];
    if (bias) {
        *(float4*)&bsv[0] = *(const float4*)&bias[bn + tn];
        *(float4*)&bsv[4] = *(const float4*)&bias[bn + tn + 4];
    }
    #pragma unroll
    for (int i = 0; i < 4; i++) {
        float r0[8], r1[8];
        #pragma unroll
        for (int j = 0; j < 8; j++) {
            float lo, hi;
            unpack2(acc2[i][j], lo, hi);
            r0[j] = lo; r1[j] = hi;
            if (bias) { r0[j] += bsv[j]; r1[j] += bsv[j]; }
        }
        float* C0 = C + (size_t)(bm + tm + 2 * i)     * N + bn + tn;
        float* C1 = C + (size_t)(bm + tm + 2 * i + 1) * N + bn + tn;
        *(float4*)(C0)     = *(float4*)&r0[0];
        *(float4*)(C0 + 4) = *(float4*)&r0[4];
        *(float4*)(C1)     = *(float4*)&r1[0];
        *(float4*)(C1 + 4) = *(float4*)&r1[4];
    }
}

// ---------------- projections -----------------------------------------------
__global__ void __launch_bounds__(256) proj_qk_kernel(
    const float* __restrict__ x,
    const float* __restrict__ Wq, const float* __restrict__ bq,
    const float* __restrict__ Wk, const float* __restrict__ bk)
{
    const float* W    = blockIdx.z ? Wk  : Wq;
    const float* bias = blockIdx.z ? bk  : bq;
    float*       Cout = blockIdx.z ? g_K : g_Q;
    sgemm_block(x, W, bias, Cout, DKDIM, DMODEL, blockIdx.y * 128, 0, 0, DMODEL);
}

__global__ void __launch_bounds__(256) proj_v_kernel(
    const float* __restrict__ x,
    const float* __restrict__ Wv, const float* __restrict__ bv)
{
    sgemm_block(x, Wv, bv, g_V, DMODEL, DMODEL,
                blockIdx.y * 128, blockIdx.x * 128, 0, DMODEL);
}

// ---------------- vmean: split-K streaming reduction ------------------------
// grid (4 col-chunks, BATCH, 16 row-chunks); atomicAdd partials.
__global__ void __launch_bounds__(256) vmean_kernel() {
    int b   = blockIdx.y;
    int col = blockIdx.x * 256 + threadIdx.x;
    int rc  = blockIdx.z;
    const float* V = g_V + ((size_t)b * S_LEN + rc * 128) * DMODEL + col;
    float s = 0.0f;
    #pragma unroll 8
    for (int k = 0; k < 128; k++) s += V[(size_t)k * DMODEL];
    atomicAdd(&g_vmean[b * DMODEL + col], s * (1.0f / S_LEN));
}

// ---------------- scores: P = Q K^T / sqrt(DK), lower-triangle tiles only ---
__global__ void __launch_bounds__(256) scores_kernel() {
    int b   = blockIdx.y;
    int idx = blockIdx.x;                 // 0..135 lower-triangle tile pairs
    int qt  = (int)((sqrtf(8.0f * idx + 1.0f) - 1.0f) * 0.5f);
    while ((qt + 1) * (qt + 2) / 2 <= idx) qt++;
    while (qt * (qt + 1) / 2 > idx) qt--;
    int kt = idx - qt * (qt + 1) / 2;

    __shared__ float As[8][128];
    __shared__ float Bs[8][128];

    const int tid  = threadIdx.x;
    const int row  = tid >> 1;
    const int col4 = (tid & 1) << 2;
    const int tm   = (tid >> 4) << 3;
    const int tn   = (tid & 15) << 3;

    const float* Qp = g_Q + ((size_t)b * S_LEN + (size_t)qt * 128 + row) * DKDIM + col4;
    const float* Kp = g_K + ((size_t)b * S_LEN + (size_t)kt * 128 + row) * DKDIM + col4;

    unsigned long long acc2[4][8];
    #pragma unroll
    for (int i = 0; i < 4; i++)
        #pragma unroll
        for (int j = 0; j < 8; j++) acc2[i][j] = 0ULL;

    for (int d0 = 0; d0 < DKDIM; d0 += 8) {
        float4 a4 = *(const float4*)(Qp + d0);
        float4 b4 = *(const float4*)(Kp + d0);
        As[col4 + 0][row] = a4.x; As[col4 + 1][row] = a4.y;
        As[col4 + 2][row] = a4.z; As[col4 + 3][row] = a4.w;
        Bs[col4 + 0][row] = b4.x; Bs[col4 + 1][row] = b4.y;
        Bs[col4 + 2][row] = b4.z; Bs[col4 + 3][row] = b4.w;
        __syncthreads();

        microtile8_f32x2(As, Bs, tm, tn, acc2);
        __syncthreads();
    }

    const float scale = 0.0883883476483184f;  // 1/sqrt(128)
    #pragma unroll
    for (int i = 0; i < 4; i++) {
        float r0[8], r1[8];
        #pragma unroll
        for (int j = 0; j < 8; j++) unpack2(acc2[i][j], r0[j], r1[j]);
        #pragma unroll
        for (int half = 0; half < 2; half++) {
            int q = qt * 128 + tm + 2 * i + half;
            const float* rr = half ? r1 : r0;
            float* Prow = g_P + ((size_t)b * S_LEN + q) * S_LEN + kt * 128 + tn;
            #pragma unroll
            for (int j = 0; j < 8; j += 4) {
                int kbase = kt * 128 + tn + j;
                float4 o;
                o.x = (kbase + 0 > q) ? -1e30f : rr[j + 0] * scale;
                o.y = (kbase + 1 > q) ? -1e30f : rr[j + 1] * scale;
                o.z = (kbase + 2 > q) ? -1e30f : rr[j + 2] * scale;
                o.w = (kbase + 3 > q) ? -1e30f : rr[j + 3] * scale;
                *(float4*)(Prow + j) = o;
            }
        }
    }
}

// ---------------- row softmax over tile-aligned prefix ----------------------
__global__ void __launch_bounds__(256) softmax_kernel() {
    __shared__ float buf[S_LEN];
    __shared__ float red[8];
    __shared__ float bcast;

    int b = blockIdx.y, q = blockIdx.x;
    int tid = threadIdx.x;
    int len = g_len[b];
    int Kend = ((q >> 7) + 1) << 7;        // tile-aligned, <= 2048
    float* row = g_P + ((size_t)b * S_LEN + q) * S_LEN;

    if (q >= len) {                        // padded query: zero the prefix
        for (int k = tid; k < Kend; k += 256) row[k] = 0.0f;
        return;
    }

    float m = -3.4e38f;
    for (int k = tid; k < Kend; k += 256) {
        float v = row[k];
        buf[k] = v;
        m = fmaxf(m, v);
    }
    #pragma unroll
    for (int off = 16; off; off >>= 1) m = fmaxf(m, __shfl_xor_sync(0xffffffffu, m, off));
    if ((tid & 31) == 0) red[tid >> 5] = m;
    __syncthreads();
    if (tid == 0) {
        float mm = red[0];
        #pragma unroll
        for (int i = 1; i < 8; i++) mm = fmaxf(mm, red[i]);
        bcast = mm;
    }
    __syncthreads();
    m = bcast;
    __syncthreads();

    float s = 0.0f;
    for (int k = tid; k < Kend; k += 256) {
        float v = (k <= q) ? __expf(buf[k] - m) : 0.0f;
        buf[k] = v;
        s += v;
    }
    #pragma unroll
    for (int off = 16; off; off >>= 1) s += __shfl_xor_sync(0xffffffffu, s, off);
    if ((tid & 31) == 0) red[tid >> 5] = s;
    __syncthreads();
    if (tid == 0) {
        float ss = red[0];
        #pragma unroll
        for (int i = 1; i < 8; i++) ss += red[i];
        bcast = 1.0f / ss;
    }
    __syncthreads();
    float inv = bcast;

    for (int k = tid; k < Kend; k += 256) row[k] = buf[k] * inv;
}

// ---------------- out = P @ V, causal-blocked --------------------------------
// Heaviest q-tiles launch first (descending work) to balance the tail wave.
__global__ void __launch_bounds__(256) pv_kernel(float* __restrict__ out) {
    int b  = blockIdx.z;
    int qt = 15 - blockIdx.y;
    const float* A = g_P + (size_t)b * S_LEN * S_LEN;
    const float* V = g_V + (size_t)b * S_LEN * DMODEL;
    float*       C = out + (size_t)b * S_LEN * DMODEL;
    sgemm_block(A, V, nullptr, C, DMODEL, S_LEN,
                qt * 128, blockIdx.x * 128, 0, (qt + 1) * 128);
}

// ---------------- overwrite padded-query rows with vmean ---------------------
__global__ void fill_padded_kernel(float* __restrict__ out) {
    int b = blockIdx.y, q = blockIdx.x;
    if (q < g_len[b]) return;
    const float* vm = g_vmean + b * DMODEL;
    float* o = out + ((size_t)b * S_LEN + q) * DMODEL;
    for (int i = threadIdx.x; i < DMODEL; i += 256) o[i] = vm[i];
}

// ---------------- launch ------------------------------------------------------
extern "C" void kernel_launch(void* const* d_in, const int* in_sizes, int n_in,
                              void* d_out, int out_size) {
    const float*         x    = (const float*)d_in[0];
    const unsigned char* mask = (const unsigned char*)d_in[1];
    const float* Wq = (const float*)d_in[2];
    const float* bq = (const float*)d_in[3];
    const float* Wk = (const float*)d_in[4];
    const float* bk = (const float*)d_in[5];
    const float* Wv = (const float*)d_in[6];
    const float* bv = (const float*)d_in[7];
    float* out = (float*)d_out;

    prep_len_kernel<<<BATCH, 256>>>(mask);
    proj_qk_kernel<<<dim3(1, 64, 2), 256>>>(x, Wq, bq, Wk, bk);
    proj_v_kernel<<<dim3(8, 64), 256>>>(x, Wv, bv);
    vmean_kernel<<<dim3(4, BATCH, 16), 256>>>();
    scores_kernel<<<dim3(136, BATCH), 256>>>();
    softmax_kernel<<<dim3(S_LEN, BATCH), 256>>>();
    pv_kernel<<<dim3(8, 16, BATCH), 256>>>(out);
    fill_padded_kernel<<<dim3(S_LEN, BATCH), 256>>>(out);
}